// round 14
// baseline (speedup 1.0000x reference)
#include <cuda_runtime.h>
#include <math.h>
#include <stdint.h>

#define N_TOKENS 262144
#define D_FEAT   1024
#define E        64
#define TOPK     8

#define BM      128
#define BK      32
#define NCHUNK  (D_FEAT / BK)   // 32
#define THREADS 256

// per-stage smem (bytes): x images 128 rows x 80B, W images 128 rows x 80B
#define XHI 0
#define XLO 10240
#define WHI 20480
#define WLO 30720
#define STAGE_B 40960           // x2 stages = 81920

#define HS_STRIDE 129
#define NS_STRIDE 65
#define SMEM_DYN 100864         // epilogue bound; 2 CTAs x 100864 = 201728 <= ~227KB

// W bf16 images: [chunk][n=128][k=32] packed (64B rows)
__device__ __align__(256) unsigned char g_WtHi[NCHUNK * 128 * 64];
__device__ __align__(256) unsigned char g_WtLo[NCHUNK * 128 * 64];

// ---------- helpers ----------
__device__ __forceinline__ uint32_t smem_u32(const void* p) {
    uint32_t a; asm("{ .reg .u64 t; cvta.to.shared.u64 t, %1; cvt.u32.u64 %0, t; }"
                    : "=r"(a) : "l"(p));
    return a;
}
__device__ __forceinline__ uint32_t f2bf2(float hi, float lo) {
    uint32_t r; asm("cvt.rn.bf16x2.f32 %0, %1, %2;" : "=r"(r) : "f"(hi), "f"(lo)); return r;
}
__device__ __forceinline__ float bfp_lo(uint32_t r) { return __uint_as_float(r << 16); }
__device__ __forceinline__ float bfp_hi(uint32_t r) { return __uint_as_float(r & 0xffff0000u); }

__device__ __forceinline__ void ldmx4(uint32_t* r, uint32_t addr) {
    asm volatile("ldmatrix.sync.aligned.m8n8.x4.shared.b16 {%0,%1,%2,%3}, [%4];"
                 : "=r"(r[0]), "=r"(r[1]), "=r"(r[2]), "=r"(r[3]) : "r"(addr));
}
__device__ __forceinline__ void mma_bf16(float* c, const uint32_t* a, const uint32_t* b) {
    asm volatile("mma.sync.aligned.m16n8k16.row.col.f32.bf16.bf16.f32 "
                 "{%0,%1,%2,%3}, {%4,%5,%6,%7}, {%8,%9}, {%0,%1,%2,%3};"
                 : "+f"(c[0]), "+f"(c[1]), "+f"(c[2]), "+f"(c[3])
                 : "r"(a[0]), "r"(a[1]), "r"(a[2]), "r"(a[3]), "r"(b[0]), "r"(b[1]));
}
__device__ __forceinline__ void cp_async16(uint32_t dst, const void* src) {
    asm volatile("cp.async.cg.shared.global [%0], [%1], 16;" :: "r"(dst), "l"(src) : "memory");
}
__device__ __forceinline__ void cp_commit() { asm volatile("cp.async.commit_group;" ::: "memory"); }
__device__ __forceinline__ void cp_wait_all() { asm volatile("cp.async.wait_group 0;" ::: "memory"); }
__device__ __forceinline__ void sts128(uint32_t addr, uint32_t a, uint32_t b, uint32_t c, uint32_t d) {
    asm volatile("st.shared.v4.b32 [%0], {%1,%2,%3,%4};" :: "r"(addr), "r"(a), "r"(b), "r"(c), "r"(d) : "memory");
}

// ---------- prep: W fp32 -> bf16 hi/lo chunk-tiled images (packed 64B rows) ----------
__global__ void prep_w_kernel(const float* __restrict__ Wg, const float* __restrict__ Wn) {
    int t = blockIdx.x * blockDim.x + threadIdx.x;   // 65536
    int j = t & 15;            // k-pair within chunk (k = 2j, 2j+1)
    int n = (t >> 4) & 127;    // output col (0..63 gate | 64..127 noise)
    int c = t >> 11;           // chunk
    int k0 = c * BK + 2 * j;
    float v0, v1;
    if (n < 64) { v0 = Wg[k0 * 64 + n];        v1 = Wg[(k0 + 1) * 64 + n]; }
    else        { v0 = Wn[k0 * 64 + (n - 64)]; v1 = Wn[(k0 + 1) * 64 + (n - 64)]; }
    uint32_t h = f2bf2(v1, v0);
    float r0 = v0 - bfp_lo(h), r1 = v1 - bfp_hi(h);
    uint32_t l = f2bf2(r1, r0);
    int off = c * 8192 + n * 64 + j * 4;
    *(uint32_t*)(g_WtHi + off) = h;
    *(uint32_t*)(g_WtLo + off) = l;
}

// ---------- main ----------
extern __shared__ char smem_raw[];

__global__ void __launch_bounds__(THREADS, 2)
moe_gate_mma_kernel(const float* __restrict__ x,
                    const float* __restrict__ noise,
                    float* __restrict__ out)
{
    char* sb = smem_raw;
    const uint32_t sbu = smem_u32(sb);
    const int tid  = threadIdx.x;
    const int warp = tid >> 5;
    const int lane = tid & 31;
    const int wm = warp & 1;      // 2 x 64-row halves
    const int wn = warp >> 1;     // 4 x 32-col blocks
    const int tok0 = blockIdx.x * BM;

    // ldmatrix lane-address components
    const int q  = lane >> 3;
    const int r8 = lane & 7;
    const int arow = ((q & 1) << 3) + r8;
    const int acol = (q >> 1) << 3;
    const int brow = ((q >> 1) << 3) + r8;
    const int bcol = (q & 1) << 3;

    float acc[4][4][4];           // [mt][nt][frag] : 64 regs
    #pragma unroll
    for (int i = 0; i < 4; i++)
        #pragma unroll
        for (int j = 0; j < 4; j++)
            #pragma unroll
            for (int k = 0; k < 4; k++) acc[i][j][k] = 0.0f;

    // x load mapping: thread -> (row = tid>>1, 16 consecutive floats at (tid&1)*16)
    const float* xrow = x + (size_t)(tok0 + (tid >> 1)) * D_FEAT + (tid & 1) * 16;
    const uint32_t x_sts_off = (uint32_t)(tid >> 1) * 80u + (uint32_t)(tid & 1) * 32u;

    float4 xr[4];

    // ---- prologue: fill stage 0 with chunk 0; preload xr with chunk 1 ----
    {
        #pragma unroll
        for (int i = 0; i < 4; i++) xr[i] = *(const float4*)(xrow + i * 4);
        #pragma unroll
        for (int i = 0; i < 2; i++) {              // 512 16B-chunks per 8KB W image
            int cid = tid + THREADS * i;
            uint32_t dst = (uint32_t)(cid >> 2) * 80u + (uint32_t)(cid & 3) * 16u;
            cp_async16(sbu + WHI + dst, g_WtHi + cid * 16);
            cp_async16(sbu + WLO + dst, g_WtLo + cid * 16);
        }
        cp_commit();
        uint32_t h[8], l[8];
        #pragma unroll
        for (int i = 0; i < 4; i++) {
            h[2*i]   = f2bf2(xr[i].y, xr[i].x);
            h[2*i+1] = f2bf2(xr[i].w, xr[i].z);
            float e0 = xr[i].x - bfp_lo(h[2*i]),   e1 = xr[i].y - bfp_hi(h[2*i]);
            float e2 = xr[i].z - bfp_lo(h[2*i+1]), e3 = xr[i].w - bfp_hi(h[2*i+1]);
            l[2*i]   = f2bf2(e1, e0);
            l[2*i+1] = f2bf2(e3, e2);
        }
        sts128(sbu + XHI + x_sts_off,      h[0], h[1], h[2], h[3]);
        sts128(sbu + XHI + x_sts_off + 16, h[4], h[5], h[6], h[7]);
        sts128(sbu + XLO + x_sts_off,      l[0], l[1], l[2], l[3]);
        sts128(sbu + XLO + x_sts_off + 16, l[4], l[5], l[6], l[7]);
        #pragma unroll
        for (int i = 0; i < 4; i++) xr[i] = *(const float4*)(xrow + BK + i * 4);
        cp_wait_all();
        __syncthreads();
    }

    // ---- main loop ----
    for (int c = 0; c < NCHUNK; ++c) {
        const uint32_t cur = sbu + (c & 1) * STAGE_B;
        const uint32_t nxt = sbu + ((c + 1) & 1) * STAGE_B;
        const bool has_next = (c + 1 < NCHUNK);

        // 1) convert xr (chunk c+1, loaded a full chunk ago) into the free buffer
        if (has_next) {
            uint32_t h[8], l[8];
            #pragma unroll
            for (int i = 0; i < 4; i++) {
                h[2*i]   = f2bf2(xr[i].y, xr[i].x);
                h[2*i+1] = f2bf2(xr[i].w, xr[i].z);
                float e0 = xr[i].x - bfp_lo(h[2*i]),   e1 = xr[i].y - bfp_hi(h[2*i]);
                float e2 = xr[i].z - bfp_lo(h[2*i+1]), e3 = xr[i].w - bfp_hi(h[2*i+1]);
                l[2*i]   = f2bf2(e1, e0);
                l[2*i+1] = f2bf2(e3, e2);
            }
            sts128(nxt + XHI + x_sts_off,      h[0], h[1], h[2], h[3]);
            sts128(nxt + XHI + x_sts_off + 16, h[4], h[5], h[6], h[7]);
            sts128(nxt + XLO + x_sts_off,      l[0], l[1], l[2], l[3]);
            sts128(nxt + XLO + x_sts_off + 16, l[4], l[5], l[6], l[7]);
            // 2) W prefetch for chunk c+1
            const unsigned char* wsrc_h = g_WtHi + (c + 1) * 8192;
            const unsigned char* wsrc_l = g_WtLo + (c + 1) * 8192;
            #pragma unroll
            for (int i = 0; i < 2; i++) {
                int cid = tid + THREADS * i;
                uint32_t dst = (uint32_t)(cid >> 2) * 80u + (uint32_t)(cid & 3) * 16u;
                cp_async16(nxt + WHI + dst, wsrc_h + cid * 16);
                cp_async16(nxt + WLO + dst, wsrc_l + cid * 16);
            }
            cp_commit();
        }
        // 3) x LDG for chunk c+2 (consumed at top of next iteration)
        if (c + 2 < NCHUNK) {
            #pragma unroll
            for (int i = 0; i < 4; i++)
                xr[i] = *(const float4*)(xrow + (c + 2) * BK + i * 4);
        }

        // 4) MMA phase: per ks, B fragments (this warp's 32 cols), then per mt A
        #pragma unroll
        for (int ks = 0; ks < 2; ++ks) {
            uint32_t bh[4][2], bl[4][2];
            #pragma unroll
            for (int bt = 0; bt < 2; ++bt) {
                uint32_t boff = (uint32_t)(wn * 32 + bt * 16 + brow) * 80u
                              + (uint32_t)(ks * 16 + bcol) * 2u;
                uint32_t tb[4];
                ldmx4(tb, cur + WHI + boff);
                bh[2*bt][0] = tb[0]; bh[2*bt][1] = tb[1];
                bh[2*bt+1][0] = tb[2]; bh[2*bt+1][1] = tb[3];
                ldmx4(tb, cur + WLO + boff);
                bl[2*bt][0] = tb[0]; bl[2*bt][1] = tb[1];
                bl[2*bt+1][0] = tb[2]; bl[2*bt+1][1] = tb[3];
            }
            #pragma unroll
            for (int mt = 0; mt < 4; ++mt) {
                uint32_t aoff = (uint32_t)(wm * 64 + mt * 16 + arow) * 80u
                              + (uint32_t)(ks * 16 + acol) * 2u;
                uint32_t ah[4], al[4];
                ldmx4(ah, cur + XHI + aoff);
                ldmx4(al, cur + XLO + aoff);
                #pragma unroll
                for (int nt = 0; nt < 4; ++nt) {
                    mma_bf16(acc[mt][nt], ah, bh[nt]);
                    mma_bf16(acc[mt][nt], ah, bl[nt]);
                    mma_bf16(acc[mt][nt], al, bh[nt]);
                }
            }
        }

        // 5) close the stage
        if (has_next) cp_wait_all();
        __syncthreads();
    }

    // ---- epilogue (aliases stage smem) ----
    float* Hs     = (float*)sb;                                 // [128][129]
    float* ns     = (float*)(sb + BM * HS_STRIDE * 4);          // [128][65]
    float* kth_s  = (float*)(sb + BM * HS_STRIDE * 4 + BM * NS_STRIDE * 4);
    float* max_s  = kth_s + BM;
    float* isum_s = max_s + BM;

    // spill accumulators
    {
        int g = lane >> 2, t4 = lane & 3;
        #pragma unroll
        for (int mt = 0; mt < 4; ++mt) {
            int row = wm * 64 + mt * 16 + g;
            #pragma unroll
            for (int nt = 0; nt < 4; ++nt) {
                int col = wn * 32 + nt * 8 + 2 * t4;
                Hs[row * HS_STRIDE + col]           = acc[mt][nt][0];
                Hs[row * HS_STRIDE + col + 1]       = acc[mt][nt][1];
                Hs[(row + 8) * HS_STRIDE + col]     = acc[mt][nt][2];
                Hs[(row + 8) * HS_STRIDE + col + 1] = acc[mt][nt][3];
            }
        }
    }
    // stage noise
    {
        const float* Nb = noise + (size_t)tok0 * E;
        for (int f = tid; f < BM * E; f += THREADS) {
            int t = f >> 6, e = f & 63;
            ns[t * NS_STRIDE + e] = Nb[f];
        }
    }
    __syncthreads();

    if (tid < BM) {
        float* hr = Hs + tid * HS_STRIDE;
        const float* nr = ns + tid * NS_STRIDE;
        #pragma unroll 4
        for (int e = 0; e < E; e++) {
            float hn = hr[64 + e];
            float sp = fmaxf(hn, 0.0f) + log1pf(expf(-fabsf(hn)));
            hr[e] = hr[e] + nr[e] * sp;
        }
        const float NEG_INF = __int_as_float(0xff800000);
        unsigned long long sel = 0ull;
        float kth = NEG_INF, m0 = NEG_INF;
        for (int s = 0; s < TOPK; s++) {
            float best = NEG_INF; int bi = 0;
            for (int e = 0; e < E; e++) {
                if (!((sel >> e) & 1ull)) {
                    float v = hr[e];
                    if (v > best) { best = v; bi = e; }
                }
            }
            sel |= 1ull << bi;
            if (s == 0) m0 = best;
            kth = best;
        }
        float sum = 0.0f;
        for (int e = 0; e < E; e++) {
            float v = hr[e];
            if (v >= kth) sum += expf(v - m0);
        }
        kth_s[tid] = kth; max_s[tid] = m0; isum_s[tid] = 1.0f / sum;
    }
    __syncthreads();

    {
        float* Ob = out + (size_t)tok0 * E;
        for (int f = tid; f < BM * E; f += THREADS) {
            int t = f >> 6, e = f & 63;
            float v = Hs[t * HS_STRIDE + e];
            Ob[f] = (v >= kth_s[t]) ? expf(v - max_s[t]) * isum_s[t] : 0.0f;
        }
    }
}

extern "C" void kernel_launch(void* const* d_in, const int* in_sizes, int n_in,
                              void* d_out, int out_size)
{
    (void)in_sizes; (void)n_in; (void)out_size;
    const float* x     = (const float*)d_in[0];
    const float* noise = (const float*)d_in[1];
    const float* Wg    = (const float*)d_in[2];
    const float* Wn    = (const float*)d_in[3];
    float* out = (float*)d_out;

    prep_w_kernel<<<256, 256>>>(Wg, Wn);

    cudaFuncSetAttribute(moe_gate_mma_kernel,
                         cudaFuncAttributeMaxDynamicSharedMemorySize, SMEM_DYN);
    moe_gate_mma_kernel<<<N_TOKENS / BM, THREADS, SMEM_DYN>>>(x, noise, out);
}

// round 15
// speedup vs baseline: 1.1942x; 1.1942x over previous
#include <cuda_runtime.h>
#include <math.h>
#include <stdint.h>

#define N_TOKENS 262144
#define D_FEAT   1024
#define E        64
#define TOPK     8

#define BM      64
#define BK      32
#define NCHUNK  (D_FEAT / BK)   // 32
#define THREADS 256

// per-stage smem layout (bytes): x images 64 rows x 80B, W images 128 rows x 80B
#define XHI 0
#define XLO 5120
#define WHI 10240
#define WLO 20480
#define STAGE_B 30720           // x2 stages = 61440

#define HS_STRIDE 129
#define NS_STRIDE 65
#define SMEM_DYN 61440          // > epilogue needs (50432); 3 CTAs x 61440 = 184KB <= 227KB

// W bf16 images: [chunk][n=128][k=32] packed (64B rows)
__device__ __align__(256) unsigned char g_WtHi[NCHUNK * 128 * 64];
__device__ __align__(256) unsigned char g_WtLo[NCHUNK * 128 * 64];

// ---------- helpers ----------
__device__ __forceinline__ uint32_t smem_u32(const void* p) {
    uint32_t a; asm("{ .reg .u64 t; cvta.to.shared.u64 t, %1; cvt.u32.u64 %0, t; }"
                    : "=r"(a) : "l"(p));
    return a;
}
__device__ __forceinline__ uint32_t f2bf2(float hi, float lo) {
    uint32_t r; asm("cvt.rn.bf16x2.f32 %0, %1, %2;" : "=r"(r) : "f"(hi), "f"(lo)); return r;
}
__device__ __forceinline__ float bfp_lo(uint32_t r) { return __uint_as_float(r << 16); }
__device__ __forceinline__ float bfp_hi(uint32_t r) { return __uint_as_float(r & 0xffff0000u); }

__device__ __forceinline__ void ldmx4(uint32_t* r, uint32_t addr) {
    asm volatile("ldmatrix.sync.aligned.m8n8.x4.shared.b16 {%0,%1,%2,%3}, [%4];"
                 : "=r"(r[0]), "=r"(r[1]), "=r"(r[2]), "=r"(r[3]) : "r"(addr));
}
__device__ __forceinline__ void mma_bf16(float* c, const uint32_t* a, const uint32_t* b) {
    asm volatile("mma.sync.aligned.m16n8k16.row.col.f32.bf16.bf16.f32 "
                 "{%0,%1,%2,%3}, {%4,%5,%6,%7}, {%8,%9}, {%0,%1,%2,%3};"
                 : "+f"(c[0]), "+f"(c[1]), "+f"(c[2]), "+f"(c[3])
                 : "r"(a[0]), "r"(a[1]), "r"(a[2]), "r"(a[3]), "r"(b[0]), "r"(b[1]));
}
__device__ __forceinline__ void cp_async16(uint32_t dst, const void* src) {
    asm volatile("cp.async.cg.shared.global [%0], [%1], 16;" :: "r"(dst), "l"(src) : "memory");
}
__device__ __forceinline__ void cp_commit() { asm volatile("cp.async.commit_group;" ::: "memory"); }
__device__ __forceinline__ void cp_wait_all() { asm volatile("cp.async.wait_group 0;" ::: "memory"); }
__device__ __forceinline__ void sts128(uint32_t addr, uint32_t a, uint32_t b, uint32_t c, uint32_t d) {
    asm volatile("st.shared.v4.b32 [%0], {%1,%2,%3,%4};" :: "r"(addr), "r"(a), "r"(b), "r"(c), "r"(d) : "memory");
}

// ---------- prep: W fp32 -> bf16 hi/lo chunk-tiled images ----------
__global__ void prep_w_kernel(const float* __restrict__ Wg, const float* __restrict__ Wn) {
    int t = blockIdx.x * blockDim.x + threadIdx.x;   // 65536
    int j = t & 15;            // k-pair within chunk (k = 2j, 2j+1)
    int n = (t >> 4) & 127;    // output col (0..63 gate | 64..127 noise)
    int c = t >> 11;           // chunk
    int k0 = c * BK + 2 * j;
    float v0, v1;
    if (n < 64) { v0 = Wg[k0 * 64 + n];        v1 = Wg[(k0 + 1) * 64 + n]; }
    else        { v0 = Wn[k0 * 64 + (n - 64)]; v1 = Wn[(k0 + 1) * 64 + (n - 64)]; }
    uint32_t h = f2bf2(v1, v0);
    float r0 = v0 - bfp_lo(h), r1 = v1 - bfp_hi(h);
    uint32_t l = f2bf2(r1, r0);
    int off = c * 8192 + n * 64 + j * 4;
    *(uint32_t*)(g_WtHi + off) = h;
    *(uint32_t*)(g_WtLo + off) = l;
}

// ---------- main ----------
extern __shared__ char smem_raw[];

__global__ void __launch_bounds__(THREADS, 3)
moe_gate_mma_kernel(const float* __restrict__ x,
                    const float* __restrict__ noise,
                    float* __restrict__ out)
{
    char* sb = smem_raw;
    const uint32_t sbu = smem_u32(sb);
    const int tid  = threadIdx.x;
    const int warp = tid >> 5;
    const int lane = tid & 31;
    const int wm = warp & 1;      // 2 x 32-row halves
    const int wn = warp >> 1;     // 4 x 32-col blocks
    const int tok0 = blockIdx.x * BM;

    // ldmatrix lane-address components
    const int q  = lane >> 3;
    const int r8 = lane & 7;
    const int arow = ((q & 1) << 3) + r8;
    const int acol = (q >> 1) << 3;
    const int brow = ((q >> 1) << 3) + r8;
    const int bcol = (q & 1) << 3;

    float acc[2][4][4];
    #pragma unroll
    for (int i = 0; i < 2; i++)
        #pragma unroll
        for (int j = 0; j < 4; j++)
            #pragma unroll
            for (int k = 0; k < 4; k++) acc[i][j][k] = 0.0f;

    // x load mapping: thread -> (row = tid>>2, 8 consecutive floats at (tid&3)*8)
    const float* xrow = x + (size_t)(tok0 + (tid >> 2)) * D_FEAT + (tid & 3) * 8;
    const uint32_t x_sts_off = (uint32_t)(tid >> 2) * 80u + (uint32_t)(tid & 3) * 16u;

    float4 xr[2];

    // ---- prologue: fill stage 0 with chunk 0; preload xr with chunk 1 ----
    {
        xr[0] = *(const float4*)(xrow);
        xr[1] = *(const float4*)(xrow + 4);
        #pragma unroll
        for (int i = 0; i < 2; i++) {              // 512 16B-chunks per 8KB W image
            int cid = tid + THREADS * i;
            uint32_t dst = (uint32_t)(cid >> 2) * 80u + (uint32_t)(cid & 3) * 16u;
            cp_async16(sbu + WHI + dst, g_WtHi + cid * 16);
            cp_async16(sbu + WLO + dst, g_WtLo + cid * 16);
        }
        cp_commit();
        uint32_t h[4], l[4];
        #pragma unroll
        for (int i = 0; i < 2; i++) {
            h[2*i]   = f2bf2(xr[i].y, xr[i].x);
            h[2*i+1] = f2bf2(xr[i].w, xr[i].z);
            float e0 = xr[i].x - bfp_lo(h[2*i]),   e1 = xr[i].y - bfp_hi(h[2*i]);
            float e2 = xr[i].z - bfp_lo(h[2*i+1]), e3 = xr[i].w - bfp_hi(h[2*i+1]);
            l[2*i]   = f2bf2(e1, e0);
            l[2*i+1] = f2bf2(e3, e2);
        }
        sts128(sbu + XHI + x_sts_off, h[0], h[1], h[2], h[3]);
        sts128(sbu + XLO + x_sts_off, l[0], l[1], l[2], l[3]);
        // preload x chunk 1 into registers (converted mid-body of chunk 0)
        xr[0] = *(const float4*)(xrow + BK);
        xr[1] = *(const float4*)(xrow + BK + 4);
        cp_wait_all();
        __syncthreads();
    }

    // ---- main loop ----
    for (int c = 0; c < NCHUNK; ++c) {
        const uint32_t cur = sbu + (c & 1) * STAGE_B;
        const uint32_t nxt = sbu + ((c + 1) & 1) * STAGE_B;
        const bool has_next = (c + 1 < NCHUNK);

        // ---- MMA ks=0 : tensor pipe starts immediately after the barrier ----
        {
            const int ks = 0;
            uint32_t bh[4][2], bl[4][2];
            #pragma unroll
            for (int bt = 0; bt < 2; ++bt) {
                uint32_t boff = (uint32_t)(wn * 32 + bt * 16 + brow) * 80u
                              + (uint32_t)(ks * 16 + bcol) * 2u;
                uint32_t tb[4];
                ldmx4(tb, cur + WHI + boff);
                bh[2*bt][0] = tb[0]; bh[2*bt][1] = tb[1];
                bh[2*bt+1][0] = tb[2]; bh[2*bt+1][1] = tb[3];
                ldmx4(tb, cur + WLO + boff);
                bl[2*bt][0] = tb[0]; bl[2*bt][1] = tb[1];
                bl[2*bt+1][0] = tb[2]; bl[2*bt+1][1] = tb[3];
            }
            #pragma unroll
            for (int mt = 0; mt < 2; ++mt) {
                uint32_t aoff = (uint32_t)(wm * 32 + mt * 16 + arow) * 80u
                              + (uint32_t)(ks * 16 + acol) * 2u;
                uint32_t ah[4], al[4];
                ldmx4(ah, cur + XHI + aoff);
                ldmx4(al, cur + XLO + aoff);
                #pragma unroll
                for (int nt = 0; nt < 4; ++nt) {
                    mma_bf16(acc[mt][nt], ah, bh[nt]);
                    mma_bf16(acc[mt][nt], ah, bl[nt]);
                    mma_bf16(acc[mt][nt], al, bh[nt]);
                }
            }
        }

        // ---- memory phase (overlaps the ks=0 HMMA drain / ks=1 window) ----
        if (has_next) {
            // convert xr (chunk c+1, loaded a full chunk ago) into the free buffer
            uint32_t h[4], l[4];
            #pragma unroll
            for (int i = 0; i < 2; i++) {
                h[2*i]   = f2bf2(xr[i].y, xr[i].x);
                h[2*i+1] = f2bf2(xr[i].w, xr[i].z);
                float e0 = xr[i].x - bfp_lo(h[2*i]),   e1 = xr[i].y - bfp_hi(h[2*i]);
                float e2 = xr[i].z - bfp_lo(h[2*i+1]), e3 = xr[i].w - bfp_hi(h[2*i+1]);
                l[2*i]   = f2bf2(e1, e0);
                l[2*i+1] = f2bf2(e3, e2);
            }
            sts128(nxt + XHI + x_sts_off, h[0], h[1], h[2], h[3]);
            sts128(nxt + XLO + x_sts_off, l[0], l[1], l[2], l[3]);
            // W prefetch for chunk c+1
            const unsigned char* wsrc_h = g_WtHi + (c + 1) * 8192;
            const unsigned char* wsrc_l = g_WtLo + (c + 1) * 8192;
            #pragma unroll
            for (int i = 0; i < 2; i++) {
                int cid = tid + THREADS * i;
                uint32_t dst = (uint32_t)(cid >> 2) * 80u + (uint32_t)(cid & 3) * 16u;
                cp_async16(nxt + WHI + dst, wsrc_h + cid * 16);
                cp_async16(nxt + WLO + dst, wsrc_l + cid * 16);
            }
            cp_commit();
        }
        // x LDG for chunk c+2 (consumed mid-body of next iteration)
        if (c + 2 < NCHUNK) {
            xr[0] = *(const float4*)(xrow + (c + 2) * BK);
            xr[1] = *(const float4*)(xrow + (c + 2) * BK + 4);
        }

        // ---- MMA ks=1 ----
        {
            const int ks = 1;
            uint32_t bh[4][2], bl[4][2];
            #pragma unroll
            for (int bt = 0; bt < 2; ++bt) {
                uint32_t boff = (uint32_t)(wn * 32 + bt * 16 + brow) * 80u
                              + (uint32_t)(ks * 16 + bcol) * 2u;
                uint32_t tb[4];
                ldmx4(tb, cur + WHI + boff);
                bh[2*bt][0] = tb[0]; bh[2*bt][1] = tb[1];
                bh[2*bt+1][0] = tb[2]; bh[2*bt+1][1] = tb[3];
                ldmx4(tb, cur + WLO + boff);
                bl[2*bt][0] = tb[0]; bl[2*bt][1] = tb[1];
                bl[2*bt+1][0] = tb[2]; bl[2*bt+1][1] = tb[3];
            }
            #pragma unroll
            for (int mt = 0; mt < 2; ++mt) {
                uint32_t aoff = (uint32_t)(wm * 32 + mt * 16 + arow) * 80u
                              + (uint32_t)(ks * 16 + acol) * 2u;
                uint32_t ah[4], al[4];
                ldmx4(ah, cur + XHI + aoff);
                ldmx4(al, cur + XLO + aoff);
                #pragma unroll
                for (int nt = 0; nt < 4; ++nt) {
                    mma_bf16(acc[mt][nt], ah, bh[nt]);
                    mma_bf16(acc[mt][nt], ah, bl[nt]);
                    mma_bf16(acc[mt][nt], al, bh[nt]);
                }
            }
        }

        // ---- close the stage ----
        if (has_next) cp_wait_all();
        __syncthreads();
    }

    // ---- epilogue (aliases stage smem) ----
    float* Hs     = (float*)sb;                                 // [64][129]
    float* ns     = (float*)(sb + BM * HS_STRIDE * 4);          // [64][65]
    float* kth_s  = (float*)(sb + BM * HS_STRIDE * 4 + BM * NS_STRIDE * 4);
    float* max_s  = kth_s + BM;
    float* isum_s = max_s + BM;

    // spill accumulators
    {
        int g = lane >> 2, t4 = lane & 3;
        #pragma unroll
        for (int mt = 0; mt < 2; ++mt) {
            int row = wm * 32 + mt * 16 + g;
            #pragma unroll
            for (int nt = 0; nt < 4; ++nt) {
                int col = wn * 32 + nt * 8 + 2 * t4;
                Hs[row * HS_STRIDE + col]           = acc[mt][nt][0];
                Hs[row * HS_STRIDE + col + 1]       = acc[mt][nt][1];
                Hs[(row + 8) * HS_STRIDE + col]     = acc[mt][nt][2];
                Hs[(row + 8) * HS_STRIDE + col + 1] = acc[mt][nt][3];
            }
        }
    }
    // stage noise
    {
        const float* Nb = noise + (size_t)tok0 * E;
        for (int f = tid; f < BM * E; f += THREADS) {
            int t = f >> 6, e = f & 63;
            ns[t * NS_STRIDE + e] = Nb[f];
        }
    }
    __syncthreads();

    if (tid < BM) {
        float* hr = Hs + tid * HS_STRIDE;
        const float* nr = ns + tid * NS_STRIDE;
        #pragma unroll 4
        for (int e = 0; e < E; e++) {
            float hn = hr[64 + e];
            float sp = fmaxf(hn, 0.0f) + log1pf(expf(-fabsf(hn)));
            hr[e] = hr[e] + nr[e] * sp;
        }
        const float NEG_INF = __int_as_float(0xff800000);
        unsigned long long sel = 0ull;
        float kth = NEG_INF, m0 = NEG_INF;
        for (int s = 0; s < TOPK; s++) {
            float best = NEG_INF; int bi = 0;
            for (int e = 0; e < E; e++) {
                if (!((sel >> e) & 1ull)) {
                    float v = hr[e];
                    if (v > best) { best = v; bi = e; }
                }
            }
            sel |= 1ull << bi;
            if (s == 0) m0 = best;
            kth = best;
        }
        float sum = 0.0f;
        for (int e = 0; e < E; e++) {
            float v = hr[e];
            if (v >= kth) sum += expf(v - m0);
        }
        kth_s[tid] = kth; max_s[tid] = m0; isum_s[tid] = 1.0f / sum;
    }
    __syncthreads();

    {
        float* Ob = out + (size_t)tok0 * E;
        for (int f = tid; f < BM * E; f += THREADS) {
            int t = f >> 6, e = f & 63;
            float v = Hs[t * HS_STRIDE + e];
            Ob[f] = (v >= kth_s[t]) ? expf(v - max_s[t]) * isum_s[t] : 0.0f;
        }
    }
}

extern "C" void kernel_launch(void* const* d_in, const int* in_sizes, int n_in,
                              void* d_out, int out_size)
{
    (void)in_sizes; (void)n_in; (void)out_size;
    const float* x     = (const float*)d_in[0];
    const float* noise = (const float*)d_in[1];
    const float* Wg    = (const float*)d_in[2];
    const float* Wn    = (const float*)d_in[3];
    float* out = (float*)d_out;

    prep_w_kernel<<<256, 256>>>(Wg, Wn);

    cudaFuncSetAttribute(moe_gate_mma_kernel,
                         cudaFuncAttributeMaxDynamicSharedMemorySize, SMEM_DYN);
    moe_gate_mma_kernel<<<N_TOKENS / BM, THREADS, SMEM_DYN>>>(x, noise, out);
}